// round 5
// baseline (speedup 1.0000x reference)
#include <cuda_runtime.h>
#include <cuda_bf16.h>

#define BSZ   512
#define TT    200
#define HID   128
#define GG    512
#define EMBD  100
#define VOC   30000
#define NCLS  9

// g_proj layout: per dir, u64[VOC][256]; entry j of row v = {col j, col j+256}
__device__ float g_proj[2][VOC * GG];
__device__ float g_h[2][BSZ * TT * HID];

typedef unsigned long long u64;

__device__ __forceinline__ u64 pk2(float lo, float hi) {
    u64 r; asm("mov.b64 %0, {%1,%2};" : "=l"(r) : "f"(lo), "f"(hi)); return r;
}
__device__ __forceinline__ void upk2(u64 v, float& lo, float& hi) {
    asm("mov.b64 {%0,%1}, %2;" : "=f"(lo), "=f"(hi) : "l"(v));
}
__device__ __forceinline__ u64 dup2(float x) { return pk2(x, x); }
__device__ __forceinline__ u64 fma2(u64 a, u64 b, u64 c) {
    u64 d; asm("fma.rn.f32x2 %0, %1, %2, %3;" : "=l"(d) : "l"(a), "l"(b), "l"(c)); return d;
}
__device__ __forceinline__ u64 add2(u64 a, u64 b) {
    u64 d; asm("add.rn.f32x2 %0, %1, %2;" : "=l"(d) : "l"(a), "l"(b)); return d;
}
__device__ __forceinline__ float sigf(float x) {
    return __fdividef(1.0f, 1.0f + __expf(-x));
}

// ---------------------------------------------------------------------------
// proj: 64x64 CTA tiles, k in two chunks of 50. block 256 = 16x16, thread
// tile 4 rows (2 pairs) x 4 cols. 4 CTAs/SM (26.4KB static smem, <=64 regs).
// grid = 469 rowtiles x 8 coltiles x 2 dirs = 7504.
// ---------------------------------------------------------------------------
#define EPS 34   // padded ep stride (u64 per k), even for 16B alignment
__global__ __launch_bounds__(256, 4)
void proj_kernel(const float* __restrict__ emb,
                 const float* __restrict__ Wf, const float* __restrict__ bf,
                 const float* __restrict__ Wb, const float* __restrict__ bb)
{
    __shared__ float Wt[50 * 64];     // [k][c]
    __shared__ u64   ep[50 * EPS];    // [k][pair]

    const int tid = threadIdx.x;
    const int tx = tid & 15;          // col group (4 cols)
    const int ty = tid >> 4;          // row group (2 pairs = 4 rows)
    const int bid = blockIdx.x;
    const int dir = bid & 1;
    const int ct  = (bid >> 1) & 7;
    const int rt  = bid >> 4;
    const int colBase = ct * 64;
    const int rowBase = rt * 64;

    const float* W    = dir ? Wb : Wf;
    const float* bias = dir ? bb : bf;
    float* out = g_proj[dir];

    u64 acc[2][4];
    #pragma unroll
    for (int c = 0; c < 4; c++) {
        u64 b2 = dup2(bias[colBase + tx * 4 + c]);
        acc[0][c] = b2; acc[1][c] = b2;
    }

    for (int k0 = 0; k0 < 100; k0 += 50) {
        for (int idx = tid; idx < 50 * 64; idx += 256) {
            int k = idx >> 6, c = idx & 63;
            Wt[idx] = W[(k0 + k) * GG + colBase + c];
        }
        for (int idx = tid; idx < 1600; idx += 256) {
            int p = idx / 50, k = idx - p * 50;
            int ra = rowBase + 2 * p, rb = ra + 1;
            float ea = (ra < VOC) ? emb[ra * EMBD + k0 + k] : 0.0f;
            float eb = (rb < VOC) ? emb[rb * EMBD + k0 + k] : 0.0f;
            ep[k * EPS + p] = pk2(ea, eb);
        }
        __syncthreads();

        #pragma unroll 5
        for (int k = 0; k < 50; k++) {
            float4 w = *(const float4*)&Wt[k * 64 + tx * 4];
            ulonglong2 e = *(const ulonglong2*)&ep[k * EPS + ty * 2];
            u64 w0 = dup2(w.x), w1 = dup2(w.y), w2 = dup2(w.z), w3 = dup2(w.w);
            acc[0][0] = fma2(e.x, w0, acc[0][0]);
            acc[0][1] = fma2(e.x, w1, acc[0][1]);
            acc[0][2] = fma2(e.x, w2, acc[0][2]);
            acc[0][3] = fma2(e.x, w3, acc[0][3]);
            acc[1][0] = fma2(e.y, w0, acc[1][0]);
            acc[1][1] = fma2(e.y, w1, acc[1][1]);
            acc[1][2] = fma2(e.y, w2, acc[1][2]);
            acc[1][3] = fma2(e.y, w3, acc[1][3]);
        }
        __syncthreads();
    }

    #pragma unroll
    for (int pp = 0; pp < 2; pp++) {
        int ra = rowBase + (ty * 2 + pp) * 2;
        int rb = ra + 1;
        #pragma unroll
        for (int c = 0; c < 4; c++) {
            int col = colBase + tx * 4 + c;
            int fo = ((col & 255) << 1) | (col >> 8);
            float oa, ob;
            upk2(acc[pp][c], oa, ob);
            if (ra < VOC) out[(size_t)ra * GG + fo] = oa;
            if (rb < VOC) out[(size_t)rb * GG + fo] = ob;
        }
    }
}

// ---------------------------------------------------------------------------
// Persistent LSTM, k-split. grid 128 = 2 dirs x 64 chunks of 8 batch rows.
// block 512: thread (j = tid&255, kg = tid>>8) computes partial z over
// k in [64kg, 64kg+64) for cols (j, j+256), all 4 row-pairs.
// U: per group 44 k in smem, 20 k in regs.
// smem: Upk[2][11][512] float4 (180224) | hpack[4][128] u64 (4096)
//       | zpart[2][4][512] u64 (32768) | tcache[8][200] int (6400) = 223488
// ---------------------------------------------------------------------------
#define KSM 44
#define KRG 20
__global__ __launch_bounds__(512, 1)
void lstm_kernel(const int* __restrict__ tokens,
                 const float* __restrict__ Uf, const float* __restrict__ Ub)
{
    extern __shared__ char sm_raw[];
    float4* Upk = (float4*)sm_raw;                  // [g][q][jj]
    u64* hpack  = (u64*)(sm_raw + 180224);          // [pair][k]
    u64* zpart  = (u64*)(sm_raw + 184320);          // [kg][pair][col]
    int* tcache = (int*)(sm_raw + 217088);

    const int tid = threadIdx.x;
    const int dir = blockIdx.x >> 6;
    const int b0  = (blockIdx.x & 63) * 8;
    const int j   = tid & 255;
    const int kg  = tid >> 8;
    const int j0 = j, j1 = j + 256;
    const int kbase = 64 * kg;
    const float* Ug = dir ? Ub : Uf;
    const u64* proju = (const u64*)g_proj[dir];
    float* hout = g_h[dir];

    // U smem: rows [64g, 64g+44) for each group g
    for (int idx = tid; idx < 2 * 11 * 512; idx += 512) {
        int g = idx / 5632;
        int rem = idx - g * 5632;
        int q = rem >> 9, jj = rem & 511;
        int kr = 64 * g + 4 * q;
        float4 v;
        v.x = Ug[(kr)     * GG + jj];
        v.y = Ug[(kr + 1) * GG + jj];
        v.z = Ug[(kr + 2) * GG + jj];
        v.w = Ug[(kr + 3) * GG + jj];
        Upk[idx] = v;
    }
    // U regs: rows [64kg+44, 64kg+64)
    float ur0[KRG], ur1[KRG];
    #pragma unroll
    for (int i = 0; i < KRG; i++) {
        ur0[i] = Ug[(kbase + KSM + i) * GG + j0];
        ur1[i] = Ug[(kbase + KSM + i) * GG + j1];
    }
    for (int idx = tid; idx < 8 * TT; idx += 512) {
        int r = idx / TT, t = idx % TT;
        tcache[idx] = tokens[(b0 + r) * TT + t];
    }
    hpack[tid & 511] = 0ULL;
    __syncthreads();

    u64 xn[8];
    if (kg == 0) {
        int t0 = dir ? (TT - 1) : 0;
        #pragma unroll
        for (int r = 0; r < 8; r++)
            xn[r] = proju[(size_t)tcache[r * TT + t0] * 256 + j];
    }

    const int m  = tid & 127;          // epilogue hidden unit
    const int pe = (tid >> 7) & 3;     // epilogue row-pair
    float cc0 = 0.0f, cc1 = 0.0f;

    for (int s = 0; s < TT; s++) {
        const int t = dir ? (TT - 1 - s) : s;

        u64 a0, a1, a2, a3, a4, a5, a6, a7;
        if (kg == 0) {
            float l0,h0,l1,h1,l2,h2,l3,h3,l4,h4,l5,h5,l6,h6,l7,h7;
            upk2(xn[0], l0, h0); upk2(xn[1], l1, h1);
            upk2(xn[2], l2, h2); upk2(xn[3], l3, h3);
            upk2(xn[4], l4, h4); upk2(xn[5], l5, h5);
            upk2(xn[6], l6, h6); upk2(xn[7], l7, h7);
            a0 = pk2(l0, l1); a1 = pk2(l2, l3); a2 = pk2(l4, l5); a3 = pk2(l6, l7);
            a4 = pk2(h0, h1); a5 = pk2(h2, h3); a6 = pk2(h4, h5); a7 = pk2(h6, h7);
            // prefetch next step's xz (hidden under the matmul)
            int sn = (s + 1 < TT) ? (s + 1) : s;
            int tn = dir ? (TT - 1 - sn) : sn;
            #pragma unroll
            for (int r = 0; r < 8; r++)
                xn[r] = proju[(size_t)tcache[r * TT + tn] * 256 + j];
        } else {
            a0 = a1 = a2 = a3 = a4 = a5 = a6 = a7 = 0ULL;
        }

        // smem U rows: 11 q-groups of 4 k
        const int ubase = kg * 11 * 512;
        float4 u0 = Upk[ubase + j0];
        float4 u1 = Upk[ubase + j1];
        #pragma unroll 1
        for (int q = 0; q < 11; q++) {
            float4 cu0 = u0, cu1 = u1;
            if (q < 10) {
                u0 = Upk[ubase + (q + 1) * 512 + j0];
                u1 = Upk[ubase + (q + 1) * 512 + j1];
            }
            const int k = kbase + 4 * q;
            ulonglong2 hA = *(const ulonglong2*)&hpack[k];
            ulonglong2 hA2= *(const ulonglong2*)&hpack[k + 2];
            ulonglong2 hB = *(const ulonglong2*)&hpack[128 + k];
            ulonglong2 hB2= *(const ulonglong2*)&hpack[128 + k + 2];
            ulonglong2 hC = *(const ulonglong2*)&hpack[256 + k];
            ulonglong2 hC2= *(const ulonglong2*)&hpack[256 + k + 2];
            ulonglong2 hD = *(const ulonglong2*)&hpack[384 + k];
            ulonglong2 hD2= *(const ulonglong2*)&hpack[384 + k + 2];
            u64 w00 = dup2(cu0.x), w01 = dup2(cu0.y), w02 = dup2(cu0.z), w03 = dup2(cu0.w);
            u64 w10 = dup2(cu1.x), w11 = dup2(cu1.y), w12 = dup2(cu1.z), w13 = dup2(cu1.w);
            a0 = fma2(hA.x,  w00, a0); a0 = fma2(hA.y,  w01, a0);
            a0 = fma2(hA2.x, w02, a0); a0 = fma2(hA2.y, w03, a0);
            a1 = fma2(hB.x,  w00, a1); a1 = fma2(hB.y,  w01, a1);
            a1 = fma2(hB2.x, w02, a1); a1 = fma2(hB2.y, w03, a1);
            a2 = fma2(hC.x,  w00, a2); a2 = fma2(hC.y,  w01, a2);
            a2 = fma2(hC2.x, w02, a2); a2 = fma2(hC2.y, w03, a2);
            a3 = fma2(hD.x,  w00, a3); a3 = fma2(hD.y,  w01, a3);
            a3 = fma2(hD2.x, w02, a3); a3 = fma2(hD2.y, w03, a3);
            a4 = fma2(hA.x,  w10, a4); a4 = fma2(hA.y,  w11, a4);
            a4 = fma2(hA2.x, w12, a4); a4 = fma2(hA2.y, w13, a4);
            a5 = fma2(hB.x,  w10, a5); a5 = fma2(hB.y,  w11, a5);
            a5 = fma2(hB2.x, w12, a5); a5 = fma2(hB2.y, w13, a5);
            a6 = fma2(hC.x,  w10, a6); a6 = fma2(hC.y,  w11, a6);
            a6 = fma2(hC2.x, w12, a6); a6 = fma2(hC2.y, w13, a6);
            a7 = fma2(hD.x,  w10, a7); a7 = fma2(hD.y,  w11, a7);
            a7 = fma2(hD2.x, w12, a7); a7 = fma2(hD2.y, w13, a7);
        }
        // register U rows: 5 groups of 4 k
        #pragma unroll
        for (int qq = 0; qq < 5; qq++) {
            const int k = kbase + KSM + 4 * qq;
            ulonglong2 hA = *(const ulonglong2*)&hpack[k];
            ulonglong2 hA2= *(const ulonglong2*)&hpack[k + 2];
            ulonglong2 hB = *(const ulonglong2*)&hpack[128 + k];
            ulonglong2 hB2= *(const ulonglong2*)&hpack[128 + k + 2];
            ulonglong2 hC = *(const ulonglong2*)&hpack[256 + k];
            ulonglong2 hC2= *(const ulonglong2*)&hpack[256 + k + 2];
            ulonglong2 hD = *(const ulonglong2*)&hpack[384 + k];
            ulonglong2 hD2= *(const ulonglong2*)&hpack[384 + k + 2];
            u64 w00 = dup2(ur0[4*qq]),   w01 = dup2(ur0[4*qq+1]);
            u64 w02 = dup2(ur0[4*qq+2]), w03 = dup2(ur0[4*qq+3]);
            u64 w10 = dup2(ur1[4*qq]),   w11 = dup2(ur1[4*qq+1]);
            u64 w12 = dup2(ur1[4*qq+2]), w13 = dup2(ur1[4*qq+3]);
            a0 = fma2(hA.x,  w00, a0); a0 = fma2(hA.y,  w01, a0);
            a0 = fma2(hA2.x, w02, a0); a0 = fma2(hA2.y, w03, a0);
            a1 = fma2(hB.x,  w00, a1); a1 = fma2(hB.y,  w01, a1);
            a1 = fma2(hB2.x, w02, a1); a1 = fma2(hB2.y, w03, a1);
            a2 = fma2(hC.x,  w00, a2); a2 = fma2(hC.y,  w01, a2);
            a2 = fma2(hC2.x, w02, a2); a2 = fma2(hC2.y, w03, a2);
            a3 = fma2(hD.x,  w00, a3); a3 = fma2(hD.y,  w01, a3);
            a3 = fma2(hD2.x, w02, a3); a3 = fma2(hD2.y, w03, a3);
            a4 = fma2(hA.x,  w10, a4); a4 = fma2(hA.y,  w11, a4);
            a4 = fma2(hA2.x, w12, a4); a4 = fma2(hA2.y, w13, a4);
            a5 = fma2(hB.x,  w10, a5); a5 = fma2(hB.y,  w11, a5);
            a5 = fma2(hB2.x, w12, a5); a5 = fma2(hB2.y, w13, a5);
            a6 = fma2(hC.x,  w10, a6); a6 = fma2(hC.y,  w11, a6);
            a6 = fma2(hC2.x, w12, a6); a6 = fma2(hC2.y, w13, a6);
            a7 = fma2(hD.x,  w10, a7); a7 = fma2(hD.y,  w11, a7);
            a7 = fma2(hD2.x, w12, a7); a7 = fma2(hD2.y, w13, a7);
        }

        // publish partial z
        {
            u64* zp = &zpart[(size_t)kg * 4 * GG];
            zp[0 * GG + j0] = a0; zp[1 * GG + j0] = a1;
            zp[2 * GG + j0] = a2; zp[3 * GG + j0] = a3;
            zp[0 * GG + j1] = a4; zp[1 * GG + j1] = a5;
            zp[2 * GG + j1] = a6; zp[3 * GG + j1] = a7;
        }
        __syncthreads();

        // epilogue: thread (m, pe) combines partials and updates rows 2pe, 2pe+1
        {
            const u64* z0 = &zpart[(size_t)pe * GG];
            const u64* z1 = &zpart[(size_t)(4 + pe) * GG];
            u64 vi = add2(z0[m],       z1[m]);
            u64 vf = add2(z0[128 + m], z1[128 + m]);
            u64 vg = add2(z0[256 + m], z1[256 + m]);
            u64 vo = add2(z0[384 + m], z1[384 + m]);
            float zi0, zi1, zf0, zf1, zg0, zg1, zo0, zo1;
            upk2(vi, zi0, zi1); upk2(vf, zf0, zf1);
            upk2(vg, zg0, zg1); upk2(vo, zo0, zo1);

            float i0 = sigf(zi0), f0 = sigf(zf0), g0 = fmaxf(zg0, 0.0f), o0 = sigf(zo0);
            float i1 = sigf(zi1), f1 = sigf(zf1), g1 = fmaxf(zg1, 0.0f), o1 = sigf(zo1);
            cc0 = f0 * cc0 + i0 * g0;
            cc1 = f1 * cc1 + i1 * g1;
            float h0 = o0 * fmaxf(cc0, 0.0f);
            float h1 = o1 * fmaxf(cc1, 0.0f);

            hout[((size_t)(b0 + 2 * pe)     * TT + t) * HID + m] = h0;
            hout[((size_t)(b0 + 2 * pe + 1) * TT + t) * HID + m] = h1;
            hpack[pe * 128 + m] = pk2(h0, h1);
        }
        __syncthreads();
    }
}

// ---------------------------------------------------------------------------
// BN + dense(256->9) + softmax. One warp per (b,t). block 256 = 8 positions.
// ---------------------------------------------------------------------------
__global__ __launch_bounds__(256, 4)
void head_kernel(const float* __restrict__ gamma, const float* __restrict__ beta,
                 const float* __restrict__ mean,  const float* __restrict__ var,
                 const float* __restrict__ Wd,    const float* __restrict__ bd,
                 float* __restrict__ out)
{
    __shared__ float scale[2 * HID], shift[2 * HID];
    __shared__ float Wsm[2 * HID * NCLS];
    __shared__ float bsm[NCLS];

    const int tid = threadIdx.x;
    {
        int d = tid;
        float rs = rsqrtf(var[d] + 1e-3f);
        float sc = rs * gamma[d];
        scale[d] = sc;
        shift[d] = beta[d] - mean[d] * sc;
        #pragma unroll
        for (int c = 0; c < NCLS; c++) Wsm[d * NCLS + c] = Wd[d * NCLS + c];
        if (tid < NCLS) bsm[tid] = bd[tid];
    }
    __syncthreads();

    const int wid  = tid >> 5;
    const int lane = tid & 31;
    const int pos  = blockIdx.x * 8 + wid;
    const int d0 = lane * 4;
    const int d1 = 128 + lane * 4;

    float4 hf = *(const float4*)&g_h[0][(size_t)pos * HID + d0];
    float4 hb = *(const float4*)&g_h[1][(size_t)pos * HID + d0];
    float v[8];
    v[0] = hf.x * scale[d0]     + shift[d0];
    v[1] = hf.y * scale[d0 + 1] + shift[d0 + 1];
    v[2] = hf.z * scale[d0 + 2] + shift[d0 + 2];
    v[3] = hf.w * scale[d0 + 3] + shift[d0 + 3];
    v[4] = hb.x * scale[d1]     + shift[d1];
    v[5] = hb.y * scale[d1 + 1] + shift[d1 + 1];
    v[6] = hb.z * scale[d1 + 2] + shift[d1 + 2];
    v[7] = hb.w * scale[d1 + 3] + shift[d1 + 3];

    float acc[NCLS];
    #pragma unroll
    for (int c = 0; c < NCLS; c++) acc[c] = 0.0f;
    #pragma unroll
    for (int i = 0; i < 8; i++) {
        int d = (i < 4) ? (d0 + i) : (d1 + i - 4);
        #pragma unroll
        for (int c = 0; c < NCLS; c++) acc[c] += v[i] * Wsm[d * NCLS + c];
    }
    #pragma unroll
    for (int off = 16; off >= 1; off >>= 1) {
        #pragma unroll
        for (int c = 0; c < NCLS; c++)
            acc[c] += __shfl_xor_sync(0xFFFFFFFFu, acc[c], off);
    }

    if (lane == 0) {
        float z[NCLS], mx = -1e30f;
        #pragma unroll
        for (int c = 0; c < NCLS; c++) { z[c] = acc[c] + bsm[c]; mx = fmaxf(mx, z[c]); }
        float sum = 0.0f;
        #pragma unroll
        for (int c = 0; c < NCLS; c++) { z[c] = __expf(z[c] - mx); sum += z[c]; }
        float inv = __fdividef(1.0f, sum);
        #pragma unroll
        for (int c = 0; c < NCLS; c++) out[(size_t)pos * NCLS + c] = z[c] * inv;
    }
}

extern "C" void kernel_launch(void* const* d_in, const int* in_sizes, int n_in,
                              void* d_out, int out_size)
{
    const int*   tokens = (const int*)d_in[0];
    const float* emb    = (const float*)d_in[1];
    const float* Wf     = (const float*)d_in[2];
    const float* Uf     = (const float*)d_in[3];
    const float* bf     = (const float*)d_in[4];
    const float* Wb     = (const float*)d_in[5];
    const float* Ub     = (const float*)d_in[6];
    const float* bb     = (const float*)d_in[7];
    const float* gamma  = (const float*)d_in[8];
    const float* beta   = (const float*)d_in[9];
    const float* mmean  = (const float*)d_in[10];
    const float* mvar   = (const float*)d_in[11];
    const float* Wd     = (const float*)d_in[12];
    const float* bd     = (const float*)d_in[13];
    float* out = (float*)d_out;

    static bool attr_done = false;
    if (!attr_done) {
        cudaFuncSetAttribute(lstm_kernel, cudaFuncAttributeMaxDynamicSharedMemorySize, 223488);
        attr_done = true;
    }

    proj_kernel<<<469 * 8 * 2, 256>>>(emb, Wf, bf, Wb, bb);
    lstm_kernel<<<128, 512, 223488>>>(tokens, Uf, Ub);
    head_kernel<<<BSZ * TT / 8, 256>>>(gamma, beta, mmean, mvar, Wd, bd, out);
}

// round 6
// speedup vs baseline: 1.0558x; 1.0558x over previous
#include <cuda_runtime.h>
#include <cuda_bf16.h>

#define BSZ   512
#define TT    200
#define HID   128
#define GG    512
#define EMBD  100
#define VOC   30000
#define NCLS  9

// g_proj layout: per dir, u64[VOC][256]; slot j of row v = {col j, col j+256}
__device__ float g_proj[2][VOC * GG];
__device__ float g_h[2][BSZ * TT * HID];

typedef unsigned long long u64;

__device__ __forceinline__ u64 pk2(float lo, float hi) {
    u64 r; asm("mov.b64 %0, {%1,%2};" : "=l"(r) : "f"(lo), "f"(hi)); return r;
}
__device__ __forceinline__ void upk2(u64 v, float& lo, float& hi) {
    asm("mov.b64 {%0,%1}, %2;" : "=f"(lo), "=f"(hi) : "l"(v));
}
__device__ __forceinline__ u64 dup2(float x) { return pk2(x, x); }
__device__ __forceinline__ u64 fma2(u64 a, u64 b, u64 c) {
    u64 d; asm("fma.rn.f32x2 %0, %1, %2, %3;" : "=l"(d) : "l"(a), "l"(b), "l"(c)); return d;
}
__device__ __forceinline__ float sigf(float x) {
    return __fdividef(1.0f, 1.0f + __expf(-x));
}

// ---------------------------------------------------------------------------
// proj v2: thread owns column PAIRS (j, j+256) -> contiguous u64 slots.
// CTA tile: 32 vocab rows x 64 slots (=128 cols). block 256 = tx16 x ty16:
// thread = 2 rows (ty*2+rr) x 4 slots (tx + 16c). k in 2 chunks of 50.
// grid = 938 rowtiles x 4 slottiles x 2 dirs = 7504. 4 CTAs/SM.
// smem: Wt2[50][64] u64 (25600B) + etp[64][52] f32 (13312B) = 38912B
// ---------------------------------------------------------------------------
#define PCH 50
__global__ __launch_bounds__(256, 4)
void proj_kernel(const float* __restrict__ emb,
                 const float* __restrict__ Wf, const float* __restrict__ bf,
                 const float* __restrict__ Wb, const float* __restrict__ bb)
{
    __shared__ u64   Wt2[PCH * 64];     // [k][slot] = {W[k][j], W[k][j+256]}
    __shared__ float etp[64 * 52];      // [row][k] padded

    const int tid = threadIdx.x;
    const int tx = tid & 15;
    const int ty = tid >> 4;
    const int bid = blockIdx.x;
    const int dir = bid & 1;
    const int ct  = (bid >> 1) & 3;
    const int rt  = bid >> 3;
    const int slotBase = ct * 64;
    const int rowBase  = rt * 32;

    const float* W    = dir ? Wb : Wf;
    const float* bias = dir ? bb : bf;
    u64* out2 = (u64*)g_proj[dir];

    u64 acc[2][4];
    #pragma unroll
    for (int c = 0; c < 4; c++) {
        int col = slotBase + tx + 16 * c;
        u64 b2 = pk2(bias[col], bias[col + 256]);
        acc[0][c] = b2; acc[1][c] = b2;
    }

    const int r0 = ty * 2;

    for (int k0 = 0; k0 < 100; k0 += PCH) {
        if (k0) __syncthreads();
        // W pairs: coalesced LDG.32 x2 per slot
        for (int idx = tid; idx < PCH * 64; idx += 256) {
            int k = idx >> 6, js = idx & 63;
            int col = slotBase + js;
            Wt2[idx] = pk2(W[(k0 + k) * GG + col], W[(k0 + k) * GG + col + 256]);
        }
        // emb tile, transposed [row][k] (coalesced along k)
        for (int idx = tid; idx < 32 * PCH; idx += 256) {
            int r = idx / PCH, k = idx - r * PCH;
            int row = rowBase + r;
            etp[r * 52 + k] = (row < VOC) ? emb[row * EMBD + k0 + k] : 0.0f;
        }
        __syncthreads();

        #pragma unroll 2
        for (int k = 0; k < PCH; k++) {
            float e0 = etp[r0 * 52 + k];
            float e1 = etp[r0 * 52 + 52 + k];
            u64 w0 = Wt2[k * 64 + tx];
            u64 w1 = Wt2[k * 64 + tx + 16];
            u64 w2 = Wt2[k * 64 + tx + 32];
            u64 w3 = Wt2[k * 64 + tx + 48];
            u64 d0 = dup2(e0), d1 = dup2(e1);
            acc[0][0] = fma2(d0, w0, acc[0][0]);
            acc[0][1] = fma2(d0, w1, acc[0][1]);
            acc[0][2] = fma2(d0, w2, acc[0][2]);
            acc[0][3] = fma2(d0, w3, acc[0][3]);
            acc[1][0] = fma2(d1, w0, acc[1][0]);
            acc[1][1] = fma2(d1, w1, acc[1][1]);
            acc[1][2] = fma2(d1, w2, acc[1][2]);
            acc[1][3] = fma2(d1, w3, acc[1][3]);
        }
    }

    #pragma unroll
    for (int rr = 0; rr < 2; rr++) {
        int row = rowBase + r0 + rr;
        if (row < VOC) {
            u64* orow = out2 + (size_t)row * 256 + slotBase;
            orow[tx]      = acc[rr][0];
            orow[tx + 16] = acc[rr][1];
            orow[tx + 32] = acc[rr][2];
            orow[tx + 48] = acc[rr][3];
        }
    }
}

// ---------------------------------------------------------------------------
// Persistent recurrent LSTM (R4 structure, best known). grid 128 = 2 dirs x
// 64 chunks of 8 batch rows. block 256; thread owns cols (tid, tid+256).
// smem: Upk[24][512] float4 | hpack[4][128] u64 | zex[4][512] u64 | tcache
// ---------------------------------------------------------------------------
__global__ __launch_bounds__(256, 1)
void lstm_kernel(const int* __restrict__ tokens,
                 const float* __restrict__ Uf, const float* __restrict__ Ub)
{
    extern __shared__ char sm_raw[];
    float4* Upk = (float4*)sm_raw;                 // 196608B
    u64* hpack  = (u64*)(sm_raw + 196608);         // 4096B
    u64* zex    = (u64*)(sm_raw + 200704);         // 16384B
    int* tcache = (int*)(sm_raw + 217088);         // 6400B

    const int tid = threadIdx.x;
    const int dir = blockIdx.x >> 6;
    const int b0  = (blockIdx.x & 63) * 8;
    const int j0 = tid, j1 = tid + 256;
    const float* Ug = dir ? Ub : Uf;
    const u64* proju = (const u64*)g_proj[dir];
    float* hout = g_h[dir];

    for (int idx = tid; idx < 24 * GG; idx += 256) {
        int q = idx >> 9, j = idx & 511;
        float4 v;
        v.x = Ug[(4 * q)     * GG + j];
        v.y = Ug[(4 * q + 1) * GG + j];
        v.z = Ug[(4 * q + 2) * GG + j];
        v.w = Ug[(4 * q + 3) * GG + j];
        Upk[idx] = v;
    }
    float ur0[32], ur1[32];
    #pragma unroll
    for (int i = 0; i < 32; i++) {
        ur0[i] = Ug[(96 + i) * GG + j0];
        ur1[i] = Ug[(96 + i) * GG + j1];
    }
    for (int idx = tid; idx < 8 * TT; idx += 256) {
        int r = idx / TT, t = idx % TT;
        tcache[idx] = tokens[(b0 + r) * TT + t];
    }
    hpack[tid] = 0ULL;
    hpack[tid + 256] = 0ULL;
    __syncthreads();

    u64 xn[8];
    {
        int t0 = dir ? (TT - 1) : 0;
        #pragma unroll
        for (int r = 0; r < 8; r++)
            xn[r] = proju[(size_t)tcache[r * TT + t0] * 256 + tid];
    }

    const int m  = tid >> 1;
    const int pb = (tid & 1) * 2;
    float cst[4] = {0.f, 0.f, 0.f, 0.f};

    for (int s = 0; s < TT; s++) {
        const int t = dir ? (TT - 1 - s) : s;

        u64 a0, a1, a2, a3, a10, a11, a12, a13;
        {
            float l0,h0,l1,h1,l2,h2,l3,h3,l4,h4,l5,h5,l6,h6,l7,h7;
            upk2(xn[0], l0, h0); upk2(xn[1], l1, h1);
            upk2(xn[2], l2, h2); upk2(xn[3], l3, h3);
            upk2(xn[4], l4, h4); upk2(xn[5], l5, h5);
            upk2(xn[6], l6, h6); upk2(xn[7], l7, h7);
            a0  = pk2(l0, l1); a1  = pk2(l2, l3); a2  = pk2(l4, l5); a3  = pk2(l6, l7);
            a10 = pk2(h0, h1); a11 = pk2(h2, h3); a12 = pk2(h4, h5); a13 = pk2(h6, h7);
        }

        {
            int sn = (s + 1 < TT) ? (s + 1) : s;
            int tn = dir ? (TT - 1 - sn) : sn;
            #pragma unroll
            for (int r = 0; r < 8; r++)
                xn[r] = proju[(size_t)tcache[r * TT + tn] * 256 + tid];
        }

        #pragma unroll 4
        for (int q = 0; q < 24; q++) {
            float4 u0 = Upk[q * GG + j0];
            float4 u1 = Upk[q * GG + j1];
            const int k = 4 * q;
            ulonglong2 hA = *(const ulonglong2*)&hpack[k];
            ulonglong2 hA2= *(const ulonglong2*)&hpack[k + 2];
            ulonglong2 hB = *(const ulonglong2*)&hpack[128 + k];
            ulonglong2 hB2= *(const ulonglong2*)&hpack[128 + k + 2];
            ulonglong2 hC = *(const ulonglong2*)&hpack[256 + k];
            ulonglong2 hC2= *(const ulonglong2*)&hpack[256 + k + 2];
            ulonglong2 hD = *(const ulonglong2*)&hpack[384 + k];
            ulonglong2 hD2= *(const ulonglong2*)&hpack[384 + k + 2];
            u64 w00 = dup2(u0.x), w01 = dup2(u0.y), w02 = dup2(u0.z), w03 = dup2(u0.w);
            u64 w10 = dup2(u1.x), w11 = dup2(u1.y), w12 = dup2(u1.z), w13 = dup2(u1.w);
            a0  = fma2(hA.x,  w00, a0);  a0  = fma2(hA.y,  w01, a0);
            a0  = fma2(hA2.x, w02, a0);  a0  = fma2(hA2.y, w03, a0);
            a1  = fma2(hB.x,  w00, a1);  a1  = fma2(hB.y,  w01, a1);
            a1  = fma2(hB2.x, w02, a1);  a1  = fma2(hB2.y, w03, a1);
            a2  = fma2(hC.x,  w00, a2);  a2  = fma2(hC.y,  w01, a2);
            a2  = fma2(hC2.x, w02, a2);  a2  = fma2(hC2.y, w03, a2);
            a3  = fma2(hD.x,  w00, a3);  a3  = fma2(hD.y,  w01, a3);
            a3  = fma2(hD2.x, w02, a3);  a3  = fma2(hD2.y, w03, a3);
            a10 = fma2(hA.x,  w10, a10); a10 = fma2(hA.y,  w11, a10);
            a10 = fma2(hA2.x, w12, a10); a10 = fma2(hA2.y, w13, a10);
            a11 = fma2(hB.x,  w10, a11); a11 = fma2(hB.y,  w11, a11);
            a11 = fma2(hB2.x, w12, a11); a11 = fma2(hB2.y, w13, a11);
            a12 = fma2(hC.x,  w10, a12); a12 = fma2(hC.y,  w11, a12);
            a12 = fma2(hC2.x, w12, a12); a12 = fma2(hC2.y, w13, a12);
            a13 = fma2(hD.x,  w10, a13); a13 = fma2(hD.y,  w11, a13);
            a13 = fma2(hD2.x, w12, a13); a13 = fma2(hD2.y, w13, a13);
        }
        #pragma unroll
        for (int qq = 0; qq < 8; qq++) {
            const int k = 96 + 4 * qq;
            ulonglong2 hA = *(const ulonglong2*)&hpack[k];
            ulonglong2 hA2= *(const ulonglong2*)&hpack[k + 2];
            ulonglong2 hB = *(const ulonglong2*)&hpack[128 + k];
            ulonglong2 hB2= *(const ulonglong2*)&hpack[128 + k + 2];
            ulonglong2 hC = *(const ulonglong2*)&hpack[256 + k];
            ulonglong2 hC2= *(const ulonglong2*)&hpack[256 + k + 2];
            ulonglong2 hD = *(const ulonglong2*)&hpack[384 + k];
            ulonglong2 hD2= *(const ulonglong2*)&hpack[384 + k + 2];
            u64 w00 = dup2(ur0[4*qq]), w01 = dup2(ur0[4*qq+1]);
            u64 w02 = dup2(ur0[4*qq+2]), w03 = dup2(ur0[4*qq+3]);
            u64 w10 = dup2(ur1[4*qq]), w11 = dup2(ur1[4*qq+1]);
            u64 w12 = dup2(ur1[4*qq+2]), w13 = dup2(ur1[4*qq+3]);
            a0  = fma2(hA.x,  w00, a0);  a0  = fma2(hA.y,  w01, a0);
            a0  = fma2(hA2.x, w02, a0);  a0  = fma2(hA2.y, w03, a0);
            a1  = fma2(hB.x,  w00, a1);  a1  = fma2(hB.y,  w01, a1);
            a1  = fma2(hB2.x, w02, a1);  a1  = fma2(hB2.y, w03, a1);
            a2  = fma2(hC.x,  w00, a2);  a2  = fma2(hC.y,  w01, a2);
            a2  = fma2(hC2.x, w02, a2);  a2  = fma2(hC2.y, w03, a2);
            a3  = fma2(hD.x,  w00, a3);  a3  = fma2(hD.y,  w01, a3);
            a3  = fma2(hD2.x, w02, a3);  a3  = fma2(hD2.y, w03, a3);
            a10 = fma2(hA.x,  w10, a10); a10 = fma2(hA.y,  w11, a10);
            a10 = fma2(hA2.x, w12, a10); a10 = fma2(hA2.y, w13, a10);
            a11 = fma2(hB.x,  w10, a11); a11 = fma2(hB.y,  w11, a11);
            a11 = fma2(hB2.x, w12, a11); a11 = fma2(hB2.y, w13, a11);
            a12 = fma2(hC.x,  w10, a12); a12 = fma2(hC.y,  w11, a12);
            a12 = fma2(hC2.x, w12, a12); a12 = fma2(hC2.y, w13, a12);
            a13 = fma2(hD.x,  w10, a13); a13 = fma2(hD.y,  w11, a13);
            a13 = fma2(hD2.x, w12, a13); a13 = fma2(hD2.y, w13, a13);
        }

        zex[0 * GG + j0] = a0;  zex[1 * GG + j0] = a1;
        zex[2 * GG + j0] = a2;  zex[3 * GG + j0] = a3;
        zex[0 * GG + j1] = a10; zex[1 * GG + j1] = a11;
        zex[2 * GG + j1] = a12; zex[3 * GG + j1] = a13;
        __syncthreads();

        {
            u64 vi0 = zex[pb * GG + m],       vi1 = zex[(pb + 1) * GG + m];
            u64 vf0 = zex[pb * GG + 128 + m], vf1 = zex[(pb + 1) * GG + 128 + m];
            u64 vg0 = zex[pb * GG + 256 + m], vg1 = zex[(pb + 1) * GG + 256 + m];
            u64 vo0 = zex[pb * GG + 384 + m], vo1 = zex[(pb + 1) * GG + 384 + m];
            float zi[4], zf[4], zg[4], zo[4], hv[4];
            upk2(vi0, zi[0], zi[1]); upk2(vi1, zi[2], zi[3]);
            upk2(vf0, zf[0], zf[1]); upk2(vf1, zf[2], zf[3]);
            upk2(vg0, zg[0], zg[1]); upk2(vg1, zg[2], zg[3]);
            upk2(vo0, zo[0], zo[1]); upk2(vo1, zo[2], zo[3]);
            #pragma unroll
            for (int r = 0; r < 4; r++) {
                float ii = sigf(zi[r]);
                float ff = sigf(zf[r]);
                float gg = fmaxf(zg[r], 0.0f);
                float oo = sigf(zo[r]);
                float c  = ff * cst[r] + ii * gg;
                cst[r] = c;
                hv[r] = oo * fmaxf(c, 0.0f);
                hout[((size_t)(b0 + 2 * pb + r) * TT + t) * HID + m] = hv[r];
            }
            hpack[pb * 128 + m]       = pk2(hv[0], hv[1]);
            hpack[(pb + 1) * 128 + m] = pk2(hv[2], hv[3]);
        }
        __syncthreads();
    }
}

// ---------------------------------------------------------------------------
// BN + dense(256->9) + softmax. One warp per (b,t). block 256 = 8 positions.
// ---------------------------------------------------------------------------
__global__ __launch_bounds__(256, 4)
void head_kernel(const float* __restrict__ gamma, const float* __restrict__ beta,
                 const float* __restrict__ mean,  const float* __restrict__ var,
                 const float* __restrict__ Wd,    const float* __restrict__ bd,
                 float* __restrict__ out)
{
    __shared__ float scale[2 * HID], shift[2 * HID];
    __shared__ float Wsm[2 * HID * NCLS];
    __shared__ float bsm[NCLS];

    const int tid = threadIdx.x;
    {
        int d = tid;
        float rs = rsqrtf(var[d] + 1e-3f);
        float sc = rs * gamma[d];
        scale[d] = sc;
        shift[d] = beta[d] - mean[d] * sc;
        #pragma unroll
        for (int c = 0; c < NCLS; c++) Wsm[d * NCLS + c] = Wd[d * NCLS + c];
        if (tid < NCLS) bsm[tid] = bd[tid];
    }
    __syncthreads();

    const int wid  = tid >> 5;
    const int lane = tid & 31;
    const int pos  = blockIdx.x * 8 + wid;
    const int d0 = lane * 4;
    const int d1 = 128 + lane * 4;

    float4 hf = *(const float4*)&g_h[0][(size_t)pos * HID + d0];
    float4 hb = *(const float4*)&g_h[1][(size_t)pos * HID + d0];
    float v[8];
    v[0] = hf.x * scale[d0]     + shift[d0];
    v[1] = hf.y * scale[d0 + 1] + shift[d0 + 1];
    v[2] = hf.z * scale[d0 + 2] + shift[d0 + 2];
    v[3] = hf.w * scale[d0 + 3] + shift[d0 + 3];
    v[4] = hb.x * scale[d1]     + shift[d1];
    v[5] = hb.y * scale[d1 + 1] + shift[d1 + 1];
    v[6] = hb.z * scale[d1 + 2] + shift[d1 + 2];
    v[7] = hb.w * scale[d1 + 3] + shift[d1 + 3];

    float acc[NCLS];
    #pragma unroll
    for (int c = 0; c < NCLS; c++) acc[c] = 0.0f;
    #pragma unroll
    for (int i = 0; i < 8; i++) {
        int d = (i < 4) ? (d0 + i) : (d1 + i - 4);
        #pragma unroll
        for (int c = 0; c < NCLS; c++) acc[c] += v[i] * Wsm[d * NCLS + c];
    }
    #pragma unroll
    for (int off = 16; off >= 1; off >>= 1) {
        #pragma unroll
        for (int c = 0; c < NCLS; c++)
            acc[c] += __shfl_xor_sync(0xFFFFFFFFu, acc[c], off);
    }

    if (lane == 0) {
        float z[NCLS], mx = -1e30f;
        #pragma unroll
        for (int c = 0; c < NCLS; c++) { z[c] = acc[c] + bsm[c]; mx = fmaxf(mx, z[c]); }
        float sum = 0.0f;
        #pragma unroll
        for (int c = 0; c < NCLS; c++) { z[c] = __expf(z[c] - mx); sum += z[c]; }
        float inv = __fdividef(1.0f, sum);
        #pragma unroll
        for (int c = 0; c < NCLS; c++) out[(size_t)pos * NCLS + c] = z[c] * inv;
    }
}

extern "C" void kernel_launch(void* const* d_in, const int* in_sizes, int n_in,
                              void* d_out, int out_size)
{
    const int*   tokens = (const int*)d_in[0];
    const float* emb    = (const float*)d_in[1];
    const float* Wf     = (const float*)d_in[2];
    const float* Uf     = (const float*)d_in[3];
    const float* bf     = (const float*)d_in[4];
    const float* Wb     = (const float*)d_in[5];
    const float* Ub     = (const float*)d_in[6];
    const float* bb     = (const float*)d_in[7];
    const float* gamma  = (const float*)d_in[8];
    const float* beta   = (const float*)d_in[9];
    const float* mmean  = (const float*)d_in[10];
    const float* mvar   = (const float*)d_in[11];
    const float* Wd     = (const float*)d_in[12];
    const float* bd     = (const float*)d_in[13];
    float* out = (float*)d_out;

    static bool attr_done = false;
    if (!attr_done) {
        cudaFuncSetAttribute(lstm_kernel, cudaFuncAttributeMaxDynamicSharedMemorySize, 223488);
        attr_done = true;
    }

    proj_kernel<<<938 * 4 * 2, 256>>>(emb, Wf, bf, Wb, bb);
    lstm_kernel<<<128, 256, 223488>>>(tokens, Uf, Ub);
    head_kernel<<<BSZ * TT / 8, 256>>>(gamma, beta, mmean, mvar, Wd, bd, out);
}